// round 4
// baseline (speedup 1.0000x reference)
#include <cuda_runtime.h>

#define NROWS 14400   // bs * Q = 16 * 900
#define NCLS  128
#define NTGT  3200
#define BT    128     // targets per block
#define BR    32      // rows per block

// Scratch (no allocations allowed) ------------------------------------------
__device__ __align__(16) float  g_ccost[NROWS * NCLS];   // focal class cost table, 7.37 MB
__device__ __align__(16) float4 g_txyxy[NTGT];
__device__ float g_tarea[NTGT];
__device__ int   g_tcls[NTGT];

// ---------------------------------------------------------------------------
// Kernel 1: per-row softmax + focal class-cost table.
// One warp per row; each lane owns 4 classes (128 = 32 lanes * 4).
// ---------------------------------------------------------------------------
__device__ __forceinline__ float focal_cc(float p) {
    float ip  = 1.0f - p;
    float pos = 0.25f * ip * ip * (-__logf(p  + 1e-8f));
    float neg = 0.75f * p  * p  * (-__logf(ip + 1e-8f));
    return pos - neg;
}

__global__ void prep_rows(const float* __restrict__ logits) {
    int warp = (blockIdx.x * blockDim.x + threadIdx.x) >> 5;
    int lane = threadIdx.x & 31;
    if (warp >= NROWS) return;

    const float4* lrow = (const float4*)(logits + (size_t)warp * NCLS);
    float4 l = lrow[lane];

    float m = fmaxf(fmaxf(l.x, l.y), fmaxf(l.z, l.w));
    #pragma unroll
    for (int o = 16; o > 0; o >>= 1) m = fmaxf(m, __shfl_xor_sync(0xffffffffu, m, o));

    float ex = __expf(l.x - m), ey = __expf(l.y - m);
    float ez = __expf(l.z - m), ew = __expf(l.w - m);
    float s = ex + ey + ez + ew;
    #pragma unroll
    for (int o = 16; o > 0; o >>= 1) s += __shfl_xor_sync(0xffffffffu, s, o);
    float rs = __fdividef(1.0f, s);

    float4 cc;
    cc.x = focal_cc(ex * rs);
    cc.y = focal_cc(ey * rs);
    cc.z = focal_cc(ez * rs);
    cc.w = focal_cc(ew * rs);
    ((float4*)(g_ccost + (size_t)warp * NCLS))[lane] = cc;
}

// ---------------------------------------------------------------------------
// Kernel 2: target-side precompute (xyxy, area, clamped class id)
// ---------------------------------------------------------------------------
__global__ void prep_tgt(const float* __restrict__ tbox,
                         const int* __restrict__ tids) {
    int i = blockIdx.x * blockDim.x + threadIdx.x;
    if (i >= NTGT) return;
    float4 b = ((const float4*)tbox)[i];
    float hw = 0.5f * b.z, hh = 0.5f * b.w;
    g_txyxy[i] = make_float4(b.x - hw, b.y - hh, b.x + hw, b.y + hh);
    g_tarea[i] = b.z * b.w;
    int c = tids[i];
    g_tcls[i] = min(max(c, 0), NCLS - 1);   // defensive clamp: never fault on bad id
}

// ---------------------------------------------------------------------------
// Kernel 3: main cost matrix.
// Grid (NTGT/BT, NROWS/BR), 256 threads. Thread tiling: 4 rows x 4 targets.
//   tx = tid&31  -> 4 contiguous targets (STG.128 output)
//   ty = tid>>5  -> 4 contiguous rows
// ---------------------------------------------------------------------------
__global__ void __launch_bounds__(256)
cost_main(const float* __restrict__ pboxes,
          const float* __restrict__ tbox,
          float* __restrict__ out) {
    __shared__ float  s_cc[BR * NCLS];   // 16 KB class-cost tables for 32 rows
    __shared__ float4 s_txyxy[BT];
    __shared__ float4 s_tc[BT];
    __shared__ float  s_ta[BT];
    __shared__ int    s_tcl[BT];

    int tid = threadIdx.x;
    int tb  = blockIdx.x * BT;
    int rb  = blockIdx.y * BR;

    // Stage row class-cost tables: 32*128 floats = 1024 float4, 4 per thread.
    {
        const float4* src = (const float4*)(g_ccost + (size_t)rb * NCLS);
        float4* dst = (float4*)s_cc;
        #pragma unroll
        for (int i = 0; i < 4; i++) dst[tid + i * 256] = src[tid + i * 256];
    }
    if (tid < BT) {
        s_txyxy[tid] = g_txyxy[tb + tid];
        s_tc[tid]    = ((const float4*)tbox)[tb + tid];
        s_ta[tid]    = g_tarea[tb + tid];
        s_tcl[tid]   = g_tcls[tb + tid];
    }
    __syncthreads();

    int tx = tid & 31, ty = tid >> 5;
    int r0 = rb + ty * 4;
    int t0 = tx * 4;

    // Row operands in registers (4 rows x 9 floats)
    float rcx[4], rcy[4], rw[4], rh[4];
    float rx0[4], ry0[4], rx1[4], ry1[4], ra[4];
    #pragma unroll
    for (int i = 0; i < 4; i++) {
        float4 b = ((const float4*)pboxes)[r0 + i];
        rcx[i] = b.x; rcy[i] = b.y; rw[i] = b.z; rh[i] = b.w;
        float hw = 0.5f * b.z, hh = 0.5f * b.w;
        rx0[i] = b.x - hw; ry0[i] = b.y - hh;
        rx1[i] = b.x + hw; ry1[i] = b.y + hh;
        ra[i]  = b.z * b.w;
    }

    // Target operands in registers (4 targets x 9 floats + class)
    float tcx[4], tcy[4], tw[4], th[4];
    float tX0[4], tY0[4], tX1[4], tY1[4], ta[4];
    int   tcl[4];
    #pragma unroll
    for (int j = 0; j < 4; j++) {
        float4 c = s_tc[t0 + j];
        tcx[j] = c.x; tcy[j] = c.y; tw[j] = c.z; th[j] = c.w;
        float4 x = s_txyxy[t0 + j];
        tX0[j] = x.x; tY0[j] = x.y; tX1[j] = x.z; tY1[j] = x.w;
        ta[j]  = s_ta[t0 + j];
        tcl[j] = s_tcl[t0 + j];
    }

    #pragma unroll
    for (int i = 0; i < 4; i++) {
        float4 o;
        float* op = &o.x;
        const float* ccrow = s_cc + (ty * 4 + i) * NCLS;
        #pragma unroll
        for (int j = 0; j < 4; j++) {
            float cc = ccrow[tcl[j]];

            // L1 box cost (cxcywh space)
            float l1 = fabsf(rcx[i] - tcx[j]) + fabsf(rcy[i] - tcy[j])
                     + fabsf(rw[i]  - tw[j])  + fabsf(rh[i]  - th[j]);

            // intersection
            float ltx = fmaxf(rx0[i], tX0[j]);
            float lty = fmaxf(ry0[i], tY0[j]);
            float rbx = fminf(rx1[i], tX1[j]);
            float rby = fminf(ry1[i], tY1[j]);
            float iw  = fmaxf(rbx - ltx, 0.0f);
            float ih  = fmaxf(rby - lty, 0.0f);
            float inter = iw * ih;
            float uni   = ra[i] + ta[j] - inter;

            // enclosing box
            float lix = fminf(rx0[i], tX0[j]);
            float liy = fminf(ry0[i], tY0[j]);
            float rix = fmaxf(rx1[i], tX1[j]);
            float riy = fmaxf(ry1[i], tY1[j]);
            float ai  = (rix - lix) * (riy - liy);

            float iou  = inter * __fdividef(1.0f, uni);
            float giou = iou - (ai - uni) * __fdividef(1.0f, ai);

            op[j] = 5.0f * l1 + cc - 2.0f * giou;
        }
        *((float4*)(out + (size_t)(r0 + i) * NTGT + tb + t0)) = o;
    }
}

// ---------------------------------------------------------------------------
extern "C" void kernel_launch(void* const* d_in, const int* in_sizes, int n_in,
                              void* d_out, int out_size) {
    const float* logits = (const float*)d_in[0];      // [16,900,128]
    const float* pboxes = (const float*)d_in[1];      // [16,900,4]
    const int*   tids   = (const int*)d_in[2];        // [3200] (int32 under jax default x64-off)
    const float* tbox   = (const float*)d_in[3];      // [3200,4]
    float* out = (float*)d_out;                       // [16,900,3200]

    prep_rows<<<NROWS / 8, 256>>>(logits);            // 8 warps/block = 8 rows
    prep_tgt<<<(NTGT + 255) / 256, 256>>>(tbox, tids);

    dim3 grid(NTGT / BT, NROWS / BR);                 // (25, 450)
    cost_main<<<grid, 256>>>(pboxes, tbox, out);
}